// round 13
// baseline (speedup 1.0000x reference)
#include <cuda_runtime.h>
#include <cuda_bf16.h>

// Problem constants
#define BATCH   64
#define IN_DIM  1024
#define OUT_DIM 1024
#define STEPS   100
#define TPROJ   99            // number of projected steps (t = 0..S-2)
#define MTOT    (TPROJ * BATCH)   // 6336 GEMM rows

// Eigen gebp kc blocking, SINGLE-THREAD branch, ARM64 l1=64KB defaults.
// classic traits: max_kc=1016 -> evened kc = 1016 - 8*floor(1007/16) = 520
// nr=8 traits:    max_kc=808  -> evened kc = 808  - 8*floor(591/16)  = 520
// (trait-independent). Partition {520, 504}; fold points after k = 520, 1024.
#define KB0 520
#define KB1 1024

// Scratch (device globals: allocation-free rule)
__device__ float g_xT[MTOT * IN_DIM];     // [m][k], m = t*64+b, K-contiguous
__device__ float g_proj[MTOT * OUT_DIM];  // [m][o]

// ---------------------------------------------------------------------------
// Kernel 1: transpose x[b][i][t] -> xT[(t*64+b)][i]
// ---------------------------------------------------------------------------
__global__ void transpose_x_kernel(const float* __restrict__ x) {
    __shared__ float tile[32][33];
    const int b  = blockIdx.z;
    const int i0 = blockIdx.y * 32;
    const int t0 = blockIdx.x * 32;

    #pragma unroll
    for (int r = threadIdx.y; r < 32; r += 8) {
        const int i = i0 + r;
        const int t = t0 + threadIdx.x;
        float v = 0.0f;
        if (t < TPROJ) v = x[(b * IN_DIM + i) * STEPS + t];
        tile[r][threadIdx.x] = v;
    }
    __syncthreads();
    #pragma unroll
    for (int r = threadIdx.y; r < 32; r += 8) {
        const int t = t0 + r;
        const int i = i0 + threadIdx.x;
        if (t < TPROJ)
            g_xT[(t * BATCH + b) * IN_DIM + i] = tile[threadIdx.x][r];
    }
}

// ---------------------------------------------------------------------------
// Kernel 2: SGEMM  proj[m][o] = sum_k xT[m][k] * W[o][k]
//
// NUMERICS CONTRACT (Eigen ST gebp blocking, l1=64KB ARM64 defaults):
//  - K split at boundaries {520, 1024} (blocks {520, 504}).
//  - Each block partial: fresh accumulator, k-ascending __fmaf_rn chain.
//    (x in {0,1}: each step is an exact add of a selected W term, so only
//    the partition + fold order affect the result.)
//  - Fold at each boundary with a separate __fadd_rn, left to right,
//    C zero-initialized (gebp C += P with alpha=1 exact; 0+P0 exact).
//  TK=8 so the k=520 fold lands on a tile boundary (520 = 65*8).
// ---------------------------------------------------------------------------
#define TM 128
#define TN 128
#define TK 8
#define SPAD 4

__global__ __launch_bounds__(256)
void sgemm_kernel(const float* __restrict__ W) {
    __shared__ float As[TK][TM + SPAD];
    __shared__ float Bs[TK][TN + SPAD];

    const int m0 = blockIdx.y * TM;
    const int n0 = blockIdx.x * TN;
    const int tid = threadIdx.x;
    const int tx = tid & 15;   // n direction
    const int ty = tid >> 4;   // m direction

    const int lk = tid & 7;    // k within tile (0..7)
    const int lr = tid >> 3;   // row base (0..31)

    float accC[8][8];   // running C (sum of completed kc-block partials)
    float part[8][8];   // current kc-block partial
    #pragma unroll
    for (int i = 0; i < 8; ++i)
        #pragma unroll
        for (int j = 0; j < 8; ++j) { accC[i][j] = 0.0f; part[i][j] = 0.0f; }

    for (int k0 = 0; k0 < IN_DIM; k0 += TK) {
        #pragma unroll
        for (int r = 0; r < 4; ++r) {
            const int m = m0 + lr + r * 32;
            As[lk][lr + r * 32] =
                (m < MTOT) ? g_xT[m * IN_DIM + k0 + lk] : 0.0f;
        }
        #pragma unroll
        for (int r = 0; r < 4; ++r) {
            const int n = n0 + lr + r * 32;
            Bs[lk][lr + r * 32] = W[n * IN_DIM + k0 + lk];
        }
        __syncthreads();

        #pragma unroll
        for (int kk = 0; kk < TK; ++kk) {
            float4 a0 = *(const float4*)&As[kk][ty * 8];
            float4 a1 = *(const float4*)&As[kk][ty * 8 + 4];
            float4 b0 = *(const float4*)&Bs[kk][tx * 8];
            float4 b1 = *(const float4*)&Bs[kk][tx * 8 + 4];
            float a[8] = {a0.x, a0.y, a0.z, a0.w, a1.x, a1.y, a1.z, a1.w};
            float b[8] = {b0.x, b0.y, b0.z, b0.w, b1.x, b1.y, b1.z, b1.w};
            #pragma unroll
            for (int i = 0; i < 8; ++i)
                #pragma unroll
                for (int j = 0; j < 8; ++j)
                    part[i][j] = __fmaf_rn(a[i], b[j], part[i][j]);
        }
        __syncthreads();

        // kc-block boundary: fold partial into running C with a plain rn add
        const int kend = k0 + TK;
        if (kend == KB0 || kend == KB1) {
            #pragma unroll
            for (int i = 0; i < 8; ++i)
                #pragma unroll
                for (int j = 0; j < 8; ++j) {
                    accC[i][j] = __fadd_rn(accC[i][j], part[i][j]);
                    part[i][j] = 0.0f;
                }
        }
    }

    #pragma unroll
    for (int i = 0; i < 8; ++i) {
        const int m = m0 + ty * 8 + i;
        if (m < MTOT) {
            float* crow = &g_proj[m * OUT_DIM + n0 + tx * 8];
            float4 v0 = make_float4(accC[i][0], accC[i][1], accC[i][2], accC[i][3]);
            float4 v1 = make_float4(accC[i][4], accC[i][5], accC[i][6], accC[i][7]);
            *(float4*)(crow)     = v0;
            *(float4*)(crow + 4) = v1;
        }
    }
}

// ---------------------------------------------------------------------------
// Kernel 3: LIF scan. One thread per (b,o) neuron.
//
// NUMERICS CONTRACT: separate rn mul/add (no FMA contraction) — matches XLA
// elementwise codegen. Select-reset is bitwise == (1-s)*Vn for positive Vn.
// ---------------------------------------------------------------------------
__global__ void lif_scan_kernel(float* __restrict__ out) {
    const int tid = blockIdx.x * blockDim.x + threadIdx.x;  // b*1024 + o
    const float a_m = 0.95f;
    const float b_m = 0.05f;
    const float a_s = 0.8f;

    float V = 0.0f, I = 0.0f;
    float* orow = out + (size_t)tid * STEPS;
    orow[0] = 0.0f;

    #pragma unroll 4
    for (int t = 0; t < TPROJ; ++t) {
        const float p  = g_proj[(size_t)t * (BATCH * OUT_DIM) + tid];
        const float Vn = __fadd_rn(__fmul_rn(a_m, V), __fmul_rn(b_m, I));
        I = __fadd_rn(__fmul_rn(a_s, I), p);
        const bool sp = (Vn > 1.0f);
        orow[t + 1] = sp ? 1.0f : 0.0f;
        V = sp ? 0.0f : Vn;
    }
}

// ---------------------------------------------------------------------------
extern "C" void kernel_launch(void* const* d_in, const int* in_sizes, int n_in,
                              void* d_out, int out_size) {
    const float* x = (const float*)d_in[0];
    const float* W = (const float*)d_in[1];
    if (in_sizes[0] == OUT_DIM * IN_DIM && in_sizes[1] == BATCH * IN_DIM * STEPS) {
        x = (const float*)d_in[1];
        W = (const float*)d_in[0];
    }
    float* out = (float*)d_out;

    {
        dim3 grid(4, IN_DIM / 32, BATCH);
        dim3 block(32, 8);
        transpose_x_kernel<<<grid, block>>>(x);
    }
    {
        dim3 grid(OUT_DIM / TN, (MTOT + TM - 1) / TM);
        sgemm_kernel<<<grid, 256>>>(W);
    }
    {
        const int threads = 256;
        const int total = BATCH * OUT_DIM;
        lif_scan_kernel<<<total / threads, threads>>>(out);
    }
}

// round 14
// speedup vs baseline: 1.1204x; 1.1204x over previous
#include <cuda_runtime.h>
#include <cuda_bf16.h>

// Problem constants
#define BATCH   64
#define IN_DIM  1024
#define OUT_DIM 1024
#define STEPS   100
#define TPROJ   99            // number of projected steps (t = 0..S-2)
#define MTOT    (TPROJ * BATCH)   // 6336 GEMM rows
#define NEUR    (BATCH * OUT_DIM) // 65536

// Eigen gebp kc blocking, SINGLE-THREAD branch, ARM64 l1=64KB defaults.
// Partition {520, 504}; fold (plain __fadd_rn) after k = 520. VERIFIED
// bitwise (rel_err == 0.0) in round 13. DO NOT change the partition or
// the k-ascending __fmaf_rn chain structure.
#define KFOLD 520

// Scratch (device globals: allocation-free rule)
__device__ float g_xT[MTOT * IN_DIM];     // [m][k], m = t*64+b, K-contiguous
__device__ float g_proj[MTOT * OUT_DIM];  // [m][o]; holds P0 between fold & end

// ---------------------------------------------------------------------------
// Kernel 1: transpose x[b][i][t] -> xT[(t*64+b)][i]
// ---------------------------------------------------------------------------
__global__ void transpose_x_kernel(const float* __restrict__ x) {
    __shared__ float tile[32][33];
    const int b  = blockIdx.z;
    const int i0 = blockIdx.y * 32;
    const int t0 = blockIdx.x * 32;

    #pragma unroll
    for (int r = threadIdx.y; r < 32; r += 8) {
        const int i = i0 + r;
        const int t = t0 + threadIdx.x;
        float v = 0.0f;
        if (t < TPROJ) v = x[(b * IN_DIM + i) * STEPS + t];
        tile[r][threadIdx.x] = v;
    }
    __syncthreads();
    #pragma unroll
    for (int r = threadIdx.y; r < 32; r += 8) {
        const int t = t0 + r;
        const int i = i0 + threadIdx.x;
        if (t < TPROJ)
            g_xT[(t * BATCH + b) * IN_DIM + i] = tile[threadIdx.x][r];
    }
}

// ---------------------------------------------------------------------------
// Kernel 2: SGEMM  proj[m][o] = sum_k xT[m][k] * W[o][k]
//
// NUMERICS CONTRACT (verified bitwise in R13):
//  - P0 = k-ascending __fmaf_rn chain over [0,520), P1 over [520,1024).
//  - proj = __fadd_rn(P0, P1).
// Implementation: single accumulator set; at k=520 (tile 32, kk=8) P0 is
// written to g_proj and acc zeroed; the final store re-reads P0 and folds.
// Double-buffered smem, register prefetch, one __syncthreads per 16-k tile.
// ---------------------------------------------------------------------------
#define TM 128
#define TN 128
#define TK 16
#define NT (IN_DIM / TK)      // 64 k-tiles
#define TFOLD 32              // tile containing k=520 (512..528)
#define SPAD 4

__global__ __launch_bounds__(256, 2)
void sgemm_kernel(const float* __restrict__ W) {
    __shared__ float As[2][TK][TM + SPAD];
    __shared__ float Bs[2][TK][TN + SPAD];

    const int m0 = blockIdx.y * TM;
    const int n0 = blockIdx.x * TN;
    const int tid = threadIdx.x;
    const int tx = tid & 15;   // n direction
    const int ty = tid >> 4;   // m direction

    const int lk = tid & 15;   // k within tile (0..15)
    const int lr = tid >> 4;   // row base (0..15)

    float acc[8][8];
    #pragma unroll
    for (int i = 0; i < 8; ++i)
        #pragma unroll
        for (int j = 0; j < 8; ++j) acc[i][j] = 0.0f;

    // preload tile 0 directly to smem buffer 0
    #pragma unroll
    for (int r = 0; r < 8; ++r) {
        const int m = m0 + lr + r * 16;
        As[0][lk][lr + r * 16] = (m < MTOT) ? g_xT[m * IN_DIM + lk] : 0.0f;
    }
    #pragma unroll
    for (int r = 0; r < 8; ++r) {
        const int n = n0 + lr + r * 16;
        Bs[0][lk][lr + r * 16] = W[n * IN_DIM + lk];
    }
    __syncthreads();

    float ra[8], rb[8];

    for (int t = 0; t < NT; ++t) {
        const int cur = t & 1;
        const int nxt = cur ^ 1;

        // prefetch next tile into registers (loads in flight during compute)
        if (t + 1 < NT) {
            const int k0n = (t + 1) * TK;
            #pragma unroll
            for (int r = 0; r < 8; ++r) {
                const int m = m0 + lr + r * 16;
                ra[r] = (m < MTOT) ? g_xT[m * IN_DIM + k0n + lk] : 0.0f;
            }
            #pragma unroll
            for (int r = 0; r < 8; ++r) {
                const int n = n0 + lr + r * 16;
                rb[r] = W[n * IN_DIM + k0n + lk];
            }
        }

        const float (*A)[TM + SPAD] = As[cur];
        const float (*B)[TN + SPAD] = Bs[cur];

        if (t == TFOLD) {
            // split tile: k 512..519, fold P0 out, then k 520..527
            #pragma unroll
            for (int kk = 0; kk < 8; ++kk) {
                float4 a0 = *(const float4*)&A[kk][ty * 8];
                float4 a1 = *(const float4*)&A[kk][ty * 8 + 4];
                float4 b0 = *(const float4*)&B[kk][tx * 8];
                float4 b1 = *(const float4*)&B[kk][tx * 8 + 4];
                float a[8] = {a0.x, a0.y, a0.z, a0.w, a1.x, a1.y, a1.z, a1.w};
                float b[8] = {b0.x, b0.y, b0.z, b0.w, b1.x, b1.y, b1.z, b1.w};
                #pragma unroll
                for (int i = 0; i < 8; ++i)
                    #pragma unroll
                    for (int j = 0; j < 8; ++j)
                        acc[i][j] = __fmaf_rn(a[i], b[j], acc[i][j]);
            }
            // write P0 to g_proj, zero acc
            #pragma unroll
            for (int i = 0; i < 8; ++i) {
                const int m = m0 + ty * 8 + i;
                if (m < MTOT) {
                    float* crow = &g_proj[m * OUT_DIM + n0 + tx * 8];
                    *(float4*)(crow) =
                        make_float4(acc[i][0], acc[i][1], acc[i][2], acc[i][3]);
                    *(float4*)(crow + 4) =
                        make_float4(acc[i][4], acc[i][5], acc[i][6], acc[i][7]);
                }
                #pragma unroll
                for (int j = 0; j < 8; ++j) acc[i][j] = 0.0f;
            }
            #pragma unroll
            for (int kk = 8; kk < TK; ++kk) {
                float4 a0 = *(const float4*)&A[kk][ty * 8];
                float4 a1 = *(const float4*)&A[kk][ty * 8 + 4];
                float4 b0 = *(const float4*)&B[kk][tx * 8];
                float4 b1 = *(const float4*)&B[kk][tx * 8 + 4];
                float a[8] = {a0.x, a0.y, a0.z, a0.w, a1.x, a1.y, a1.z, a1.w};
                float b[8] = {b0.x, b0.y, b0.z, b0.w, b1.x, b1.y, b1.z, b1.w};
                #pragma unroll
                for (int i = 0; i < 8; ++i)
                    #pragma unroll
                    for (int j = 0; j < 8; ++j)
                        acc[i][j] = __fmaf_rn(a[i], b[j], acc[i][j]);
            }
        } else {
            #pragma unroll
            for (int kk = 0; kk < TK; ++kk) {
                float4 a0 = *(const float4*)&A[kk][ty * 8];
                float4 a1 = *(const float4*)&A[kk][ty * 8 + 4];
                float4 b0 = *(const float4*)&B[kk][tx * 8];
                float4 b1 = *(const float4*)&B[kk][tx * 8 + 4];
                float a[8] = {a0.x, a0.y, a0.z, a0.w, a1.x, a1.y, a1.z, a1.w};
                float b[8] = {b0.x, b0.y, b0.z, b0.w, b1.x, b1.y, b1.z, b1.w};
                #pragma unroll
                for (int i = 0; i < 8; ++i)
                    #pragma unroll
                    for (int j = 0; j < 8; ++j)
                        acc[i][j] = __fmaf_rn(a[i], b[j], acc[i][j]);
            }
        }

        // stage prefetched tile into the next buffer
        if (t + 1 < NT) {
            #pragma unroll
            for (int r = 0; r < 8; ++r) As[nxt][lk][lr + r * 16] = ra[r];
            #pragma unroll
            for (int r = 0; r < 8; ++r) Bs[nxt][lk][lr + r * 16] = rb[r];
        }
        __syncthreads();
    }

    // final: proj = fadd(P0, P1) ; P0 was parked in g_proj
    #pragma unroll
    for (int i = 0; i < 8; ++i) {
        const int m = m0 + ty * 8 + i;
        if (m < MTOT) {
            float* crow = &g_proj[m * OUT_DIM + n0 + tx * 8];
            float4 p0a = *(const float4*)(crow);
            float4 p0b = *(const float4*)(crow + 4);
            float4 v0 = make_float4(__fadd_rn(p0a.x, acc[i][0]),
                                    __fadd_rn(p0a.y, acc[i][1]),
                                    __fadd_rn(p0a.z, acc[i][2]),
                                    __fadd_rn(p0a.w, acc[i][3]));
            float4 v1 = make_float4(__fadd_rn(p0b.x, acc[i][4]),
                                    __fadd_rn(p0b.y, acc[i][5]),
                                    __fadd_rn(p0b.z, acc[i][6]),
                                    __fadd_rn(p0b.w, acc[i][7]));
            *(float4*)(crow)     = v0;
            *(float4*)(crow + 4) = v1;
        }
    }
}

// ---------------------------------------------------------------------------
// Kernel 3: LIF scan, warp-transposed coalesced output.
// Each warp owns 32 consecutive neurons. Spikes for a 32-column chunk of the
// output are collected as bits in a per-thread mask; __shfl broadcasts each
// neuron's mask so the warp writes contiguous 32-float rows (coalesced).
//
// NUMERICS CONTRACT (verified bitwise in R13): separate __fmul_rn/__fadd_rn,
// no FMA contraction; select-reset. Recurrence ops unchanged, only the
// output addressing differs.
// ---------------------------------------------------------------------------
__global__ void lif_scan_kernel(float* __restrict__ out) {
    const int lane = threadIdx.x & 31;
    const int warp = (blockIdx.x * blockDim.x + threadIdx.x) >> 5;
    const int n0   = warp * 32;        // first neuron of this warp
    const int nid  = n0 + lane;

    const float a_m = 0.95f;
    const float b_m = 0.05f;
    const float a_s = 0.8f;

    float V = 0.0f, I = 0.0f;
    int t = 0;   // spike step; out column j corresponds to step j-1

    #pragma unroll
    for (int c = 0; c < 4; ++c) {
        const int jlo   = (c == 0) ? 1 : 0;   // column 0 is the zero step
        const int ncols = (c == 3) ? 4 : 32;  // last chunk: columns 96..99
        unsigned mask = 0u;

        for (int j = jlo; j < ncols; ++j) {
            const float p  = g_proj[(size_t)t * NEUR + nid];
            const float Vn = __fadd_rn(__fmul_rn(a_m, V), __fmul_rn(b_m, I));
            I = __fadd_rn(__fmul_rn(a_s, I), p);
            const bool sp = (Vn > 1.0f);
            mask |= (sp ? 1u : 0u) << j;
            V = sp ? 0.0f : Vn;
            ++t;
        }

        const int cbase = c * 32;
        #pragma unroll
        for (int r = 0; r < 32; ++r) {
            const unsigned m = __shfl_sync(0xffffffffu, mask, r);
            if (lane < ncols)
                out[(size_t)(n0 + r) * STEPS + cbase + lane] =
                    ((m >> lane) & 1u) ? 1.0f : 0.0f;
        }
    }
}

// ---------------------------------------------------------------------------
extern "C" void kernel_launch(void* const* d_in, const int* in_sizes, int n_in,
                              void* d_out, int out_size) {
    const float* x = (const float*)d_in[0];
    const float* W = (const float*)d_in[1];
    if (in_sizes[0] == OUT_DIM * IN_DIM && in_sizes[1] == BATCH * IN_DIM * STEPS) {
        x = (const float*)d_in[1];
        W = (const float*)d_in[0];
    }
    float* out = (float*)d_out;

    {
        dim3 grid(4, IN_DIM / 32, BATCH);
        dim3 block(32, 8);
        transpose_x_kernel<<<grid, block>>>(x);
    }
    {
        dim3 grid(OUT_DIM / TN, (MTOT + TM - 1) / TM);
        sgemm_kernel<<<grid, 256>>>(W);
    }
    {
        const int threads = 256;
        const int blocks = NEUR / threads;   // 256 blocks, 8 warps each
        lif_scan_kernel<<<blocks, threads>>>(out);
    }
}